// round 9
// baseline (speedup 1.0000x reference)
#include <cuda_runtime.h>
#include <cuda_bf16.h>
#include <cstdint>
#include <math.h>

// Problem constants
#define Bc   64
#define Tc   512
#define Fc   128
#define Hc   512
#define G4   2048
#define Nf   32768          // flattened (t,b) columns = Tc*Bc
#define NCTA 128            // persistent CTAs for recurrent kernel

// ---------------------------------------------------------------------------
// Scratch (device globals)
// ---------------------------------------------------------------------------
__device__ __align__(16) float         g_xproj[(size_t)G4 * Nf];      // [2048][32768] 256 MB
__device__ __align__(16) __nv_bfloat16 g_hsHi[(size_t)Nf * Hc];       // [t*64+b][u]
__device__ __align__(16) __nv_bfloat16 g_hsLo[(size_t)Nf * Hc];
__device__ __align__(16) __nv_bfloat16 g_Whi[(size_t)G4 * Hc];        // reused per layer
__device__ __align__(16) __nv_bfloat16 g_Wlo[(size_t)G4 * Hc];
__device__ __align__(16) __nv_bfloat16 g_Xhi[(size_t)Nf * Fc];        // layer-0 input
__device__ __align__(16) __nv_bfloat16 g_Xlo[(size_t)Nf * Fc];
__device__ __align__(16) float         g_hT[2 * Hc * Bc];             // h ping-pong fp32
__device__ __align__(16) float         g_h1[64 * Bc];
__device__ unsigned g_barGen;
__device__ unsigned g_barCount;

// ---------------------------------------------------------------------------
// PTX helpers (arch-agnostic ISA only: valid at compute_103)
// ---------------------------------------------------------------------------
__device__ __forceinline__ uint32_t smem_u32(const void* p) {
    uint32_t a;
    asm("{ .reg .u64 t; cvta.to.shared.u64 t, %1; cvt.u32.u64 %0, t; }" : "=r"(a) : "l"(p));
    return a;
}
#define CPA(dst, src) asm volatile("cp.async.ca.shared.global [%0], [%1], 16;" :: "r"(dst), "l"(src))
#define CPCOMMIT()    asm volatile("cp.async.commit_group;" ::: "memory")
#define CPWAIT0()     asm volatile("cp.async.wait_group 0;" ::: "memory")
#define CPWAIT1()     asm volatile("cp.async.wait_group 1;" ::: "memory")

__device__ __forceinline__ void ldsm4(uint32_t* r, uint32_t a) {
    asm volatile("ldmatrix.sync.aligned.m8n8.x4.shared.b16 {%0,%1,%2,%3}, [%4];"
                 : "=r"(r[0]), "=r"(r[1]), "=r"(r[2]), "=r"(r[3]) : "r"(a));
}
__device__ __forceinline__ void mma16816(float* c, const uint32_t* a, uint32_t b0, uint32_t b1) {
    asm volatile("mma.sync.aligned.m16n8k16.row.col.f32.bf16.bf16.f32 "
                 "{%0,%1,%2,%3}, {%4,%5,%6,%7}, {%8,%9}, {%0,%1,%2,%3};"
                 : "+f"(c[0]), "+f"(c[1]), "+f"(c[2]), "+f"(c[3])
                 : "r"(a[0]), "r"(a[1]), "r"(a[2]), "r"(a[3]), "r"(b0), "r"(b1));
}

// ---------------------------------------------------------------------------
// fp32 -> bf16 hi/lo split
// ---------------------------------------------------------------------------
__global__ void split_bf16(const float* __restrict__ src,
                           __nv_bfloat16* __restrict__ hi,
                           __nv_bfloat16* __restrict__ lo, int n)
{
    int i = blockIdx.x * 256 + threadIdx.x;
    if (i < n) {
        float x = src[i];
        __nv_bfloat16 h = __float2bfloat16(x);
        hi[i] = h;
        lo[i] = __float2bfloat16(x - __bfloat162float(h));
    }
}

// ---------------------------------------------------------------------------
// Tensor-core (mma.sync bf16) xproj GEMM:
//   out[g][n] = sum_k W[g,k]*X[n,k] + bih[g]+bhh[g]
// bf16 2-split: hi*hi + hi*lo + lo*hi, fp32 accum.
// CTA 128x128, K-chunk 64, cp.async double buffer, 8 warps (2m x 4n),
// warp tile 64x32 = 4x4 m16n8k16 tiles. XOR-16B swizzled smem; the same
// lane->address pattern feeds ldmatrix.x4 for A (m16k16) and B (two n8k16).
// ---------------------------------------------------------------------------
#define OFF_AH 0u
#define OFF_AL 16384u
#define OFF_BH 32768u
#define OFF_BL 49152u
#define BUFSTR 65536u
#define GEMM_SMEM (2u * BUFSTR)   // 131072 bytes

__device__ __forceinline__ void gemm_issue(
    uint32_t base, const __nv_bfloat16* __restrict__ Ahi, const __nv_bfloat16* __restrict__ Alo,
    const __nv_bfloat16* __restrict__ Bhi, const __nv_bfloat16* __restrict__ Blo,
    int g0, int n0, int kb, int K, int tid)
{
#pragma unroll
    for (int j = 0; j < 4; ++j) {
        int i = tid + j * 256;          // 0..1023
        int r = i >> 3;                 // 0..127
        int c16 = i & 7;                // 16B chunk within 128B row
        uint32_t so = (uint32_t)(r * 128 + ((c16 ^ (r & 7)) << 4));
        size_t ga = (size_t)(g0 + r) * K + kb + c16 * 8;
        size_t gb = (size_t)(n0 + r) * K + kb + c16 * 8;
        CPA(base + OFF_AH + so, Ahi + ga);
        CPA(base + OFF_AL + so, Alo + ga);
        CPA(base + OFF_BH + so, Bhi + gb);
        CPA(base + OFF_BL + so, Blo + gb);
    }
}

__global__ void __launch_bounds__(256, 1)
gemm_tc(const __nv_bfloat16* __restrict__ Ahi, const __nv_bfloat16* __restrict__ Alo,
        const __nv_bfloat16* __restrict__ Bhi, const __nv_bfloat16* __restrict__ Blo,
        const float* __restrict__ bih, const float* __restrict__ bhh,
        float* __restrict__ out, int K)
{
    extern __shared__ char smem[];
    const uint32_t sb = smem_u32(smem);
    const int tid = threadIdx.x, wid = tid >> 5, lid = tid & 31;
    const int g0 = blockIdx.x * 128;
    const int n0 = blockIdx.y * 128;
    const int wm = wid & 1;             // 0..1  -> 64 rows
    const int wn = wid >> 1;            // 0..3  -> 32 cols

    float acc[4][4][4];
#pragma unroll
    for (int a = 0; a < 4; ++a)
#pragma unroll
        for (int b = 0; b < 4; ++b)
#pragma unroll
            for (int c = 0; c < 4; ++c) acc[a][b][c] = 0.f;

    const int nk = K >> 6;

    gemm_issue(sb, Ahi, Alo, Bhi, Blo, g0, n0, 0, K, tid);
    CPCOMMIT();

    // lane address components (shared by A and B ldmatrix.x4 patterns)
    const int lrow = lid & 15;
    const int lchunk = lid >> 4;        // 0..1 -> +16B

    for (int kc = 0; kc < nk; ++kc) {
        if (kc + 1 < nk) {
            gemm_issue(sb + ((kc + 1) & 1) * BUFSTR, Ahi, Alo, Bhi, Blo,
                       g0, n0, (kc + 1) << 6, K, tid);
            CPCOMMIT();
            CPWAIT1();
        } else {
            CPWAIT0();
        }
        __syncthreads();

        const uint32_t buf = sb + (kc & 1) * BUFSTR;
#pragma unroll
        for (int ks = 0; ks < 4; ++ks) {
            const int c16 = ks * 2 + lchunk;
            uint32_t ah[4][4], al[4][4];
#pragma unroll
            for (int mt = 0; mt < 4; ++mt) {
                int row = wm * 64 + mt * 16 + lrow;
                uint32_t so = (uint32_t)(row * 128 + ((c16 ^ (row & 7)) << 4));
                ldsm4(ah[mt], buf + OFF_AH + so);
                ldsm4(al[mt], buf + OFF_AL + so);
            }
            uint32_t bh[2][4], bl[2][4];
#pragma unroll
            for (int hlf = 0; hlf < 2; ++hlf) {
                int row = wn * 32 + hlf * 16 + lrow;
                uint32_t so = (uint32_t)(row * 128 + ((c16 ^ (row & 7)) << 4));
                ldsm4(bh[hlf], buf + OFF_BH + so);
                ldsm4(bl[hlf], buf + OFF_BL + so);
            }
#pragma unroll
            for (int mt = 0; mt < 4; ++mt) {
#pragma unroll
                for (int nt = 0; nt < 4; ++nt) {
                    const int hlf = nt >> 1, ix = nt & 1;
                    mma16816(acc[mt][nt], ah[mt], bh[hlf][ix], bh[hlf][ix + 2]);
                    mma16816(acc[mt][nt], ah[mt], bl[hlf][ix], bl[hlf][ix + 2]);
                    mma16816(acc[mt][nt], al[mt], bh[hlf][ix], bh[hlf][ix + 2]);
                }
            }
        }
        __syncthreads();
    }

    // epilogue: fused bias, float2 stores to out[g][n]
    const int colb = n0 + wn * 32 + (lid & 3) * 2;
#pragma unroll
    for (int mt = 0; mt < 4; ++mt) {
        int gA = g0 + wm * 64 + mt * 16 + (lid >> 2);
        int gB = gA + 8;
        float biasA = __ldg(bih + gA) + __ldg(bhh + gA);
        float biasB = __ldg(bih + gB) + __ldg(bhh + gB);
        float* pA = out + (size_t)gA * Nf + colb;
        float* pB = out + (size_t)gB * Nf + colb;
#pragma unroll
        for (int nt = 0; nt < 4; ++nt) {
            float2 vA = make_float2(acc[mt][nt][0] + biasA, acc[mt][nt][1] + biasA);
            float2 vB = make_float2(acc[mt][nt][2] + biasB, acc[mt][nt][3] + biasB);
            *(float2*)(pA + nt * 8) = vA;
            *(float2*)(pB + nt * 8) = vB;
        }
    }
}

// ---------------------------------------------------------------------------
// Grid-wide software barrier (all NCTA CTAs resident)
// ---------------------------------------------------------------------------
__device__ __forceinline__ void grid_barrier()
{
    __syncthreads();
    if (threadIdx.x == 0) {
        __threadfence();
        volatile unsigned* vgen = &g_barGen;
        unsigned gen = *vgen;
        unsigned ticket = atomicAdd(&g_barCount, 1u);
        if (ticket == NCTA - 1) {
            g_barCount = 0;
            __threadfence();
            *vgen = gen + 1u;
        } else {
            while (*vgen == gen) { }
            __threadfence();
        }
    }
    __syncthreads();
}

__device__ __forceinline__ float sigmoidf_(float x) { return 1.f / (1.f + __expf(-x)); }

// ---------------------------------------------------------------------------
// Persistent fp32 recurrent kernel. xproj layout [g][n] with
// n = l0 ? b*512 + t : t*64 + b. Writes h as bf16 hi/lo at [t*64+b][u].
// ---------------------------------------------------------------------------
__global__ void __launch_bounds__(256, 1)
lstm_rec(const float* __restrict__ xproj, const float* __restrict__ Whh,
         __nv_bfloat16* __restrict__ hsHi, __nv_bfloat16* __restrict__ hsLo, int l0)
{
    extern __shared__ float smf[];
    float* sW = smf;                    // 8192 floats [k*16+r]
    float* sH = smf + 8192;             // 2 x 8192 floats
    float* sG = smf + 8192 + 16384;     // 1024 floats
    float* sC = sG + 1024;              // 256 floats

    const int tid = threadIdx.x;
    const int b   = tid & 63;
    const int q   = tid >> 6;
    const int u0  = blockIdx.x << 2;

    for (int j = 0; j < 32; ++j) {
        int idx = j * 256 + tid;
        int r = idx >> 9;
        int k = idx & 511;
        sW[k * 16 + r] = Whh[(size_t)((r >> 2) * Hc + u0 + (r & 3)) * Hc + k];
    }
    sC[q * 64 + b] = 0.f;
    g_hT[(u0 + q) * 64 + b] = 0.f;

    // prefetch xproj for t=0
    float accN[4];
    {
        int nidx = l0 ? (b * 512) : b;
#pragma unroll
        for (int m = 0; m < 4; ++m)
            accN[m] = __ldcs(xproj + (size_t)(q * Hc + u0 + m) * Nf + nidx);
    }
    __syncthreads();
    grid_barrier();

    const float* wbase = sW + q * 4;
    float4 pre[8];

    for (int t = 0; t < Tc; ++t) {
        float acc[4] = {accN[0], accN[1], accN[2], accN[3]};

        const float* hin  = g_hT + ((t & 1) ? (Hc * Bc) : 0);
        float*       hout = g_hT + ((t & 1) ? 0 : (Hc * Bc));

#pragma unroll
        for (int j = 0; j < 8; ++j)
            pre[j] = __ldcg((const float4*)hin + j * 256 + tid);

        for (int c = 0; c < 4; ++c) {
            __syncthreads();
            float* sHc = sH + (c & 1) * 8192;
#pragma unroll
            for (int j = 0; j < 8; ++j)
                *((float4*)sHc + j * 256 + tid) = pre[j];
            __syncthreads();
            if (c < 3) {
#pragma unroll
                for (int j = 0; j < 8; ++j)
                    pre[j] = __ldcg((const float4*)hin + (c + 1) * 2048 + j * 256 + tid);
            }
            const float* wc = wbase + (c * 128) * 16;
            const float* hc = sHc + b;
#pragma unroll 8
            for (int kl = 0; kl < 128; ++kl) {
                float  hk = hc[kl * 64];
                float4 w  = *(const float4*)(wc + kl * 16);
                acc[0] += hk * w.x;
                acc[1] += hk * w.y;
                acc[2] += hk * w.z;
                acc[3] += hk * w.w;
            }
        }

#pragma unroll
        for (int m = 0; m < 4; ++m)
            sG[q * 256 + m * 64 + b] = acc[m];
        __syncthreads();

        float gi = sigmoidf_(sG[0 * 256 + q * 64 + b]);
        float gf = sigmoidf_(sG[1 * 256 + q * 64 + b]);
        float gg = tanhf(sG[2 * 256 + q * 64 + b]);
        float go = sigmoidf_(sG[3 * 256 + q * 64 + b]);
        float cv = gf * sC[q * 64 + b] + gi * gg;
        sC[q * 64 + b] = cv;
        float hv = go * tanhf(cv);

        hout[(u0 + q) * 64 + b] = hv;
        __nv_bfloat16 hh = __float2bfloat16(hv);
        size_t hsi = ((size_t)t * 64 + b) * Hc + u0 + q;
        hsHi[hsi] = hh;
        hsLo[hsi] = __float2bfloat16(hv - __bfloat162float(hh));

        // prefetch next step's xproj before the barrier (independent of h)
        if (t + 1 < Tc) {
            int nidx = l0 ? (b * 512 + t + 1) : ((t + 1) * 64 + b);
#pragma unroll
            for (int m = 0; m < 4; ++m)
                accN[m] = __ldcs(xproj + (size_t)(q * Hc + u0 + m) * Nf + nidx);
        }
        grid_barrier();
    }
}

// ---------------------------------------------------------------------------
// FC head (reads last-step h from bf16 hi/lo)
// ---------------------------------------------------------------------------
__global__ void fc1_kernel(const __nv_bfloat16* __restrict__ hsHi,
                           const __nv_bfloat16* __restrict__ hsLo,
                           const float* __restrict__ W1, const float* __restrict__ b1,
                           float* __restrict__ h1)
{
    int idx = blockIdx.x * 256 + threadIdx.x;   // 0..4095
    int j = idx >> 6;
    int b = idx & 63;
    const __nv_bfloat16* ph = hsHi + ((size_t)(Tc - 1) * 64 + b) * Hc;
    const __nv_bfloat16* pl = hsLo + ((size_t)(Tc - 1) * 64 + b) * Hc;
    float v = b1[j];
    for (int h = 0; h < Hc; ++h)
        v += W1[j * Hc + h] * (__bfloat162float(ph[h]) + __bfloat162float(pl[h]));
    h1[j * 64 + b] = fmaxf(v, 0.f);
}

__global__ void fc2_kernel(const float* __restrict__ h1,
                           const float* __restrict__ W2, const float* __restrict__ b2,
                           float* __restrict__ out)
{
    int b = threadIdx.x;
    float v = b2[0];
    for (int j = 0; j < 64; ++j)
        v += W2[j] * h1[j * 64 + b];
    out[b] = fmaxf(v, 0.f);
}

// ---------------------------------------------------------------------------
// Launch
// ---------------------------------------------------------------------------
#define REC_SMEM ((8192 + 16384 + 1024 + 256) * 4)   // 103424 bytes

extern "C" void kernel_launch(void* const* d_in, const int* in_sizes, int n_in,
                              void* d_out, int out_size)
{
    const float* x    = (const float*)d_in[0];
    const float* Wih0 = (const float*)d_in[1];
    const float* Whh0 = (const float*)d_in[2];
    const float* bih0 = (const float*)d_in[3];
    const float* bhh0 = (const float*)d_in[4];
    const float* Wih1 = (const float*)d_in[5];
    const float* Whh1 = (const float*)d_in[6];
    const float* bih1 = (const float*)d_in[7];
    const float* bhh1 = (const float*)d_in[8];
    const float* Wih2 = (const float*)d_in[9];
    const float* Whh2 = (const float*)d_in[10];
    const float* bih2 = (const float*)d_in[11];
    const float* bhh2 = (const float*)d_in[12];
    const float* W1   = (const float*)d_in[13];
    const float* b1   = (const float*)d_in[14];
    const float* W2   = (const float*)d_in[15];
    const float* b2   = (const float*)d_in[16];

    float *xproj, *h1;
    __nv_bfloat16 *hsHi, *hsLo, *Whi, *Wlo, *Xhi, *Xlo;
    cudaGetSymbolAddress((void**)&xproj, g_xproj);
    cudaGetSymbolAddress((void**)&h1,   g_h1);
    cudaGetSymbolAddress((void**)&hsHi, g_hsHi);
    cudaGetSymbolAddress((void**)&hsLo, g_hsLo);
    cudaGetSymbolAddress((void**)&Whi,  g_Whi);
    cudaGetSymbolAddress((void**)&Wlo,  g_Wlo);
    cudaGetSymbolAddress((void**)&Xhi,  g_Xhi);
    cudaGetSymbolAddress((void**)&Xlo,  g_Xlo);

    cudaFuncSetAttribute(gemm_tc,  cudaFuncAttributeMaxDynamicSharedMemorySize, GEMM_SMEM);
    cudaFuncSetAttribute(lstm_rec, cudaFuncAttributeMaxDynamicSharedMemorySize, REC_SMEM);

    dim3 gg(16, 256);

    // ---- Layer 0 (K = 128; xproj columns n = b*512 + t) ----
    split_bf16<<<(G4 * Fc + 255) / 256, 256>>>(Wih0, Whi, Wlo, G4 * Fc);
    split_bf16<<<(Nf * Fc + 255) / 256, 256>>>(x, Xhi, Xlo, Nf * Fc);
    gemm_tc<<<gg, 256, GEMM_SMEM>>>(Whi, Wlo, Xhi, Xlo, bih0, bhh0, xproj, Fc);
    lstm_rec<<<NCTA, 256, REC_SMEM>>>(xproj, Whh0, hsHi, hsLo, 1);

    // ---- Layer 1 (K = 512; xproj columns n = t*64 + b) ----
    split_bf16<<<(G4 * Hc + 255) / 256, 256>>>(Wih1, Whi, Wlo, G4 * Hc);
    gemm_tc<<<gg, 256, GEMM_SMEM>>>(Whi, Wlo, hsHi, hsLo, bih1, bhh1, xproj, Hc);
    lstm_rec<<<NCTA, 256, REC_SMEM>>>(xproj, Whh1, hsHi, hsLo, 0);

    // ---- Layer 2 ----
    split_bf16<<<(G4 * Hc + 255) / 256, 256>>>(Wih2, Whi, Wlo, G4 * Hc);
    gemm_tc<<<gg, 256, GEMM_SMEM>>>(Whi, Wlo, hsHi, hsLo, bih2, bhh2, xproj, Hc);
    lstm_rec<<<NCTA, 256, REC_SMEM>>>(xproj, Whh2, hsHi, hsLo, 0);

    // ---- FC head ----
    fc1_kernel<<<16, 256>>>(hsHi, hsLo, W1, b1, h1);
    fc2_kernel<<<1, 64>>>(h1, W2, b2, (float*)d_out);
}

// round 10
// speedup vs baseline: 1.4905x; 1.4905x over previous
#include <cuda_runtime.h>
#include <cuda_bf16.h>
#include <cstdint>
#include <math.h>

// Problem constants
#define Bc   64
#define Tc   512
#define Fc   128
#define Hc   512
#define G4   2048
#define Nf   32768          // flattened (t,b) columns = Tc*Bc
#define NCTA 128            // persistent CTAs for recurrent kernel

// ---------------------------------------------------------------------------
// Scratch (device globals)
// ---------------------------------------------------------------------------
__device__ __align__(16) float         g_xproj[(size_t)G4 * Nf];      // [2048][32768] 256 MB
__device__ __align__(16) __nv_bfloat16 g_hsHi[(size_t)Nf * Hc];       // [t*64+b][u]
__device__ __align__(16) __nv_bfloat16 g_hsLo[(size_t)Nf * Hc];
__device__ __align__(16) __nv_bfloat16 g_Whi[(size_t)G4 * Hc];        // reused per layer
__device__ __align__(16) __nv_bfloat16 g_Wlo[(size_t)G4 * Hc];
__device__ __align__(16) __nv_bfloat16 g_Xhi[(size_t)Nf * Fc];        // layer-0 input
__device__ __align__(16) __nv_bfloat16 g_Xlo[(size_t)Nf * Fc];
__device__ __align__(16) __nv_bfloat16 g_hHiT[2][Bc * Hc];            // h ping-pong [buf][b][u]
__device__ __align__(16) __nv_bfloat16 g_hLoT[2][Bc * Hc];
__device__ __align__(16) float         g_h1[64 * Bc];
__device__ unsigned g_barGen;
__device__ unsigned g_barCount;

// ---------------------------------------------------------------------------
// PTX helpers (arch-agnostic ISA only: valid at compute_103)
// ---------------------------------------------------------------------------
__device__ __forceinline__ uint32_t smem_u32(const void* p) {
    uint32_t a;
    asm("{ .reg .u64 t; cvta.to.shared.u64 t, %1; cvt.u32.u64 %0, t; }" : "=r"(a) : "l"(p));
    return a;
}
#define CPA(dst, src)  asm volatile("cp.async.ca.shared.global [%0], [%1], 16;" :: "r"(dst), "l"(src))
#define CPAG(dst, src) asm volatile("cp.async.cg.shared.global [%0], [%1], 16;" :: "r"(dst), "l"(src))
#define CPCOMMIT()    asm volatile("cp.async.commit_group;" ::: "memory")
#define CPWAIT0()     asm volatile("cp.async.wait_group 0;" ::: "memory")
#define CPWAIT1()     asm volatile("cp.async.wait_group 1;" ::: "memory")

__device__ __forceinline__ void ldsm4(uint32_t* r, uint32_t a) {
    asm volatile("ldmatrix.sync.aligned.m8n8.x4.shared.b16 {%0,%1,%2,%3}, [%4];"
                 : "=r"(r[0]), "=r"(r[1]), "=r"(r[2]), "=r"(r[3]) : "r"(a));
}
__device__ __forceinline__ void mma16816(float* c, const uint32_t* a, uint32_t b0, uint32_t b1) {
    asm volatile("mma.sync.aligned.m16n8k16.row.col.f32.bf16.bf16.f32 "
                 "{%0,%1,%2,%3}, {%4,%5,%6,%7}, {%8,%9}, {%0,%1,%2,%3};"
                 : "+f"(c[0]), "+f"(c[1]), "+f"(c[2]), "+f"(c[3])
                 : "r"(a[0]), "r"(a[1]), "r"(a[2]), "r"(a[3]), "r"(b0), "r"(b1));
}

// ---------------------------------------------------------------------------
// fp32 -> bf16 hi/lo split
// ---------------------------------------------------------------------------
__global__ void split_bf16(const float* __restrict__ src,
                           __nv_bfloat16* __restrict__ hi,
                           __nv_bfloat16* __restrict__ lo, int n)
{
    int i = blockIdx.x * 256 + threadIdx.x;
    if (i < n) {
        float x = src[i];
        __nv_bfloat16 h = __float2bfloat16(x);
        hi[i] = h;
        lo[i] = __float2bfloat16(x - __bfloat162float(h));
    }
}

// ---------------------------------------------------------------------------
// Tensor-core (mma.sync bf16) xproj GEMM (unchanged from round 9):
//   out[g][n] = sum_k W[g,k]*X[n,k] + bih[g]+bhh[g]
// ---------------------------------------------------------------------------
#define OFF_AH 0u
#define OFF_AL 16384u
#define OFF_BH 32768u
#define OFF_BL 49152u
#define BUFSTR 65536u
#define GEMM_SMEM (2u * BUFSTR)   // 131072 bytes

__device__ __forceinline__ void gemm_issue(
    uint32_t base, const __nv_bfloat16* __restrict__ Ahi, const __nv_bfloat16* __restrict__ Alo,
    const __nv_bfloat16* __restrict__ Bhi, const __nv_bfloat16* __restrict__ Blo,
    int g0, int n0, int kb, int K, int tid)
{
#pragma unroll
    for (int j = 0; j < 4; ++j) {
        int i = tid + j * 256;          // 0..1023
        int r = i >> 3;                 // 0..127
        int c16 = i & 7;                // 16B chunk within 128B row
        uint32_t so = (uint32_t)(r * 128 + ((c16 ^ (r & 7)) << 4));
        size_t ga = (size_t)(g0 + r) * K + kb + c16 * 8;
        size_t gb = (size_t)(n0 + r) * K + kb + c16 * 8;
        CPA(base + OFF_AH + so, Ahi + ga);
        CPA(base + OFF_AL + so, Alo + ga);
        CPA(base + OFF_BH + so, Bhi + gb);
        CPA(base + OFF_BL + so, Blo + gb);
    }
}

__global__ void __launch_bounds__(256, 1)
gemm_tc(const __nv_bfloat16* __restrict__ Ahi, const __nv_bfloat16* __restrict__ Alo,
        const __nv_bfloat16* __restrict__ Bhi, const __nv_bfloat16* __restrict__ Blo,
        const float* __restrict__ bih, const float* __restrict__ bhh,
        float* __restrict__ out, int K)
{
    extern __shared__ char smem[];
    const uint32_t sb = smem_u32(smem);
    const int tid = threadIdx.x, wid = tid >> 5, lid = tid & 31;
    const int g0 = blockIdx.x * 128;
    const int n0 = blockIdx.y * 128;
    const int wm = wid & 1;             // 0..1  -> 64 rows
    const int wn = wid >> 1;            // 0..3  -> 32 cols

    float acc[4][4][4];
#pragma unroll
    for (int a = 0; a < 4; ++a)
#pragma unroll
        for (int b = 0; b < 4; ++b)
#pragma unroll
            for (int c = 0; c < 4; ++c) acc[a][b][c] = 0.f;

    const int nk = K >> 6;

    gemm_issue(sb, Ahi, Alo, Bhi, Blo, g0, n0, 0, K, tid);
    CPCOMMIT();

    const int lrow = lid & 15;
    const int lchunk = lid >> 4;        // 0..1 -> +16B

    for (int kc = 0; kc < nk; ++kc) {
        if (kc + 1 < nk) {
            gemm_issue(sb + ((kc + 1) & 1) * BUFSTR, Ahi, Alo, Bhi, Blo,
                       g0, n0, (kc + 1) << 6, K, tid);
            CPCOMMIT();
            CPWAIT1();
        } else {
            CPWAIT0();
        }
        __syncthreads();

        const uint32_t buf = sb + (kc & 1) * BUFSTR;
#pragma unroll
        for (int ks = 0; ks < 4; ++ks) {
            const int c16 = ks * 2 + lchunk;
            uint32_t ah[4][4], al[4][4];
#pragma unroll
            for (int mt = 0; mt < 4; ++mt) {
                int row = wm * 64 + mt * 16 + lrow;
                uint32_t so = (uint32_t)(row * 128 + ((c16 ^ (row & 7)) << 4));
                ldsm4(ah[mt], buf + OFF_AH + so);
                ldsm4(al[mt], buf + OFF_AL + so);
            }
            uint32_t bh[2][4], bl[2][4];
#pragma unroll
            for (int hlf = 0; hlf < 2; ++hlf) {
                int row = wn * 32 + hlf * 16 + lrow;
                uint32_t so = (uint32_t)(row * 128 + ((c16 ^ (row & 7)) << 4));
                ldsm4(bh[hlf], buf + OFF_BH + so);
                ldsm4(bl[hlf], buf + OFF_BL + so);
            }
#pragma unroll
            for (int mt = 0; mt < 4; ++mt) {
#pragma unroll
                for (int nt = 0; nt < 4; ++nt) {
                    const int hlf = nt >> 1, ix = nt & 1;
                    mma16816(acc[mt][nt], ah[mt], bh[hlf][ix], bh[hlf][ix + 2]);
                    mma16816(acc[mt][nt], ah[mt], bl[hlf][ix], bl[hlf][ix + 2]);
                    mma16816(acc[mt][nt], al[mt], bh[hlf][ix], bh[hlf][ix + 2]);
                }
            }
        }
        __syncthreads();
    }

    const int colb = n0 + wn * 32 + (lid & 3) * 2;
#pragma unroll
    for (int mt = 0; mt < 4; ++mt) {
        int gA = g0 + wm * 64 + mt * 16 + (lid >> 2);
        int gB = gA + 8;
        float biasA = __ldg(bih + gA) + __ldg(bhh + gA);
        float biasB = __ldg(bih + gB) + __ldg(bhh + gB);
        float* pA = out + (size_t)gA * Nf + colb;
        float* pB = out + (size_t)gB * Nf + colb;
#pragma unroll
        for (int nt = 0; nt < 4; ++nt) {
            float2 vA = make_float2(acc[mt][nt][0] + biasA, acc[mt][nt][1] + biasA);
            float2 vB = make_float2(acc[mt][nt][2] + biasB, acc[mt][nt][3] + biasB);
            *(float2*)(pA + nt * 8) = vA;
            *(float2*)(pB + nt * 8) = vB;
        }
    }
}

// ---------------------------------------------------------------------------
// Grid-wide software barrier (all NCTA CTAs resident)
// ---------------------------------------------------------------------------
__device__ __forceinline__ void grid_barrier()
{
    __syncthreads();
    if (threadIdx.x == 0) {
        __threadfence();
        volatile unsigned* vgen = &g_barGen;
        unsigned gen = *vgen;
        unsigned ticket = atomicAdd(&g_barCount, 1u);
        if (ticket == NCTA - 1) {
            g_barCount = 0;
            __threadfence();
            *vgen = gen + 1u;
        } else {
            while (*vgen == gen) { }
            __threadfence();
        }
    }
    __syncthreads();
}

__device__ __forceinline__ float sigmoidf_(float x) { return 1.f / (1.f + __expf(-x)); }

// ---------------------------------------------------------------------------
// Persistent recurrent kernel, mma.sync edition.
// 128 CTAs x 256 threads. CTA owns 4 hidden units u0..u0+3 -> 16 gate rows
// (row r: gate = r>>2, unit = u0 + (r&3)).
// A = Whh slice [16][512] bf16 hi/lo, resident in smem (padded stride 520,
// conflict-free fragment LDS). B = h^T [64 b][512 k] bf16 hi/lo, staged from
// a global ping-pong via cp.async.cg each step. 8 warps split K (64 each),
// 96 HMMA each (3-split), partials reduced through smem. c state in register.
// ---------------------------------------------------------------------------
#define RS_AHI 0
#define RS_ALO 16640
#define RS_BHI 33280
#define RS_BLO 99840
#define RS_RED 166400
#define REC_SMEM 200192

__global__ void __launch_bounds__(256, 1)
lstm_rec(const float* __restrict__ xproj, const float* __restrict__ Whh,
         __nv_bfloat16* __restrict__ hsHi, __nv_bfloat16* __restrict__ hsLo, int l0)
{
    extern __shared__ char smem[];
    const uint32_t sbase = smem_u32(smem);
    __nv_bfloat16* sAhi = (__nv_bfloat16*)(smem + RS_AHI);   // [16][520]
    __nv_bfloat16* sAlo = (__nv_bfloat16*)(smem + RS_ALO);
    const __nv_bfloat16* sBhi = (const __nv_bfloat16*)(smem + RS_BHI);  // [64][520]
    const __nv_bfloat16* sBlo = (const __nv_bfloat16*)(smem + RS_BLO);
    float* sRed = (float*)(smem + RS_RED);                    // 8 x [16][66]

    const int tid = threadIdx.x;
    const int w   = tid >> 5;
    const int l   = tid & 31;
    const int u0  = blockIdx.x << 2;
    const int eb  = tid >> 2;       // elementwise: batch
    const int eu  = tid & 3;        // elementwise: unit offset
    const int u   = u0 + eu;

    // Load + split Whh slice into smem (once)
    for (int j = 0; j < 32; ++j) {
        int idx = j * 256 + tid;    // 0..8191
        int r = idx >> 9;           // 0..15
        int k = idx & 511;
        float wv = Whh[(size_t)((r >> 2) * Hc + u0 + (r & 3)) * Hc + k];
        __nv_bfloat16 hb = __float2bfloat16(wv);
        sAhi[r * 520 + k] = hb;
        sAlo[r * 520 + k] = __float2bfloat16(wv - __bfloat162float(hb));
    }
    // zero h buffer 0 (our slice)
    g_hHiT[0][eb * Hc + u] = __float2bfloat16(0.f);
    g_hLoT[0][eb * Hc + u] = __float2bfloat16(0.f);

    float c_reg = 0.f;
    // prefetch xproj for t=0
    float xp[4];
    {
        int nidx = l0 ? (eb * 512) : eb;
#pragma unroll
        for (int gt = 0; gt < 4; ++gt)
            xp[gt] = __ldcs(xproj + (size_t)(gt * Hc + u) * Nf + nidx);
    }
    __syncthreads();
    grid_barrier();

    const int rq = l >> 2;          // fragment quad-row 0..7
    const int kq = (l & 3) * 2;     // fragment k offset
    const int kb = w * 64;          // warp K-range base
    float* sRedW = sRed + w * 1056; // warp partial area [16][66]

    for (int t = 0; t < Tc; ++t) {
        // ---- stage h (hi+lo) from global ping-pong into smem ----
        {
            const char* srcHi = (const char*)g_hHiT[t & 1];
            const char* srcLo = (const char*)g_hLoT[t & 1];
#pragma unroll
            for (int j = 0; j < 16; ++j) {
                int ch = tid + j * 256;       // 0..4095
                int row = ch >> 6;
                int c16 = ch & 63;
                uint32_t dof = (uint32_t)(row * 1040 + c16 * 16);
                uint32_t sof = (uint32_t)(row * 1024 + c16 * 16);
                CPAG(sbase + RS_BHI + dof, srcHi + sof);
                CPAG(sbase + RS_BLO + dof, srcLo + sof);
            }
            CPCOMMIT();
            CPWAIT0();
            __syncthreads();
        }

        // ---- warp GEMM over its K range ----
        float acc[8][4];
#pragma unroll
        for (int nb = 0; nb < 8; ++nb)
#pragma unroll
            for (int c = 0; c < 4; ++c) acc[nb][c] = 0.f;

#pragma unroll
        for (int ks = 0; ks < 4; ++ks) {
            int k0 = kb + ks * 16 + kq;
            uint32_t ah[4], al[4];
            ah[0] = *(const uint32_t*)(sAhi + rq * 520 + k0);
            ah[1] = *(const uint32_t*)(sAhi + (rq + 8) * 520 + k0);
            ah[2] = *(const uint32_t*)(sAhi + rq * 520 + k0 + 8);
            ah[3] = *(const uint32_t*)(sAhi + (rq + 8) * 520 + k0 + 8);
            al[0] = *(const uint32_t*)(sAlo + rq * 520 + k0);
            al[1] = *(const uint32_t*)(sAlo + (rq + 8) * 520 + k0);
            al[2] = *(const uint32_t*)(sAlo + rq * 520 + k0 + 8);
            al[3] = *(const uint32_t*)(sAlo + (rq + 8) * 520 + k0 + 8);
#pragma unroll
            for (int nb = 0; nb < 8; ++nb) {
                int n = nb * 8 + rq;
                uint32_t bh0 = *(const uint32_t*)(sBhi + n * 520 + k0);
                uint32_t bh1 = *(const uint32_t*)(sBhi + n * 520 + k0 + 8);
                uint32_t bl0 = *(const uint32_t*)(sBlo + n * 520 + k0);
                uint32_t bl1 = *(const uint32_t*)(sBlo + n * 520 + k0 + 8);
                mma16816(acc[nb], ah, bh0, bh1);
                mma16816(acc[nb], al, bh0, bh1);
                mma16816(acc[nb], ah, bl0, bl1);
            }
        }

        // ---- store warp partials ----
#pragma unroll
        for (int nb = 0; nb < 8; ++nb) {
            int cc = nb * 8 + (l & 3) * 2;
            *(float2*)(sRedW + rq * 66 + cc)       = make_float2(acc[nb][0], acc[nb][1]);
            *(float2*)(sRedW + (rq + 8) * 66 + cc) = make_float2(acc[nb][2], acc[nb][3]);
        }
        __syncthreads();

        // ---- reduce + elementwise (thread = (eu, eb)) ----
        float gate[4];
#pragma unroll
        for (int gt = 0; gt < 4; ++gt) {
            float s = 0.f;
            int roff = (gt * 4 + eu) * 66 + eb;
#pragma unroll
            for (int ww = 0; ww < 8; ++ww)
                s += sRed[ww * 1056 + roff];
            gate[gt] = s + xp[gt];
        }
        float gi = sigmoidf_(gate[0]);
        float gf = sigmoidf_(gate[1]);
        float gg = tanhf(gate[2]);
        float go = sigmoidf_(gate[3]);
        c_reg = gf * c_reg + gi * gg;
        float hv = go * tanhf(c_reg);

        __nv_bfloat16 hh = __float2bfloat16(hv);
        __nv_bfloat16 hl = __float2bfloat16(hv - __bfloat162float(hh));
        int nxt = (t + 1) & 1;
        g_hHiT[nxt][eb * Hc + u] = hh;
        g_hLoT[nxt][eb * Hc + u] = hl;
        size_t hsi = ((size_t)t * 64 + eb) * Hc + u;
        hsHi[hsi] = hh;
        hsLo[hsi] = hl;

        // prefetch next step's xproj (independent of h)
        if (t + 1 < Tc) {
            int nidx = l0 ? (eb * 512 + t + 1) : ((t + 1) * 64 + eb);
#pragma unroll
            for (int gt = 0; gt < 4; ++gt)
                xp[gt] = __ldcs(xproj + (size_t)(gt * Hc + u) * Nf + nidx);
        }
        grid_barrier();
    }
}

// ---------------------------------------------------------------------------
// FC head (reads last-step h from bf16 hi/lo)
// ---------------------------------------------------------------------------
__global__ void fc1_kernel(const __nv_bfloat16* __restrict__ hsHi,
                           const __nv_bfloat16* __restrict__ hsLo,
                           const float* __restrict__ W1, const float* __restrict__ b1,
                           float* __restrict__ h1)
{
    int idx = blockIdx.x * 256 + threadIdx.x;   // 0..4095
    int j = idx >> 6;
    int b = idx & 63;
    const __nv_bfloat16* ph = hsHi + ((size_t)(Tc - 1) * 64 + b) * Hc;
    const __nv_bfloat16* pl = hsLo + ((size_t)(Tc - 1) * 64 + b) * Hc;
    float v = b1[j];
    for (int h = 0; h < Hc; ++h)
        v += W1[j * Hc + h] * (__bfloat162float(ph[h]) + __bfloat162float(pl[h]));
    h1[j * 64 + b] = fmaxf(v, 0.f);
}

__global__ void fc2_kernel(const float* __restrict__ h1,
                           const float* __restrict__ W2, const float* __restrict__ b2,
                           float* __restrict__ out)
{
    int b = threadIdx.x;
    float v = b2[0];
    for (int j = 0; j < 64; ++j)
        v += W2[j] * h1[j * 64 + b];
    out[b] = fmaxf(v, 0.f);
}

// ---------------------------------------------------------------------------
// Launch
// ---------------------------------------------------------------------------
extern "C" void kernel_launch(void* const* d_in, const int* in_sizes, int n_in,
                              void* d_out, int out_size)
{
    const float* x    = (const float*)d_in[0];
    const float* Wih0 = (const float*)d_in[1];
    const float* Whh0 = (const float*)d_in[2];
    const float* bih0 = (const float*)d_in[3];
    const float* bhh0 = (const float*)d_in[4];
    const float* Wih1 = (const float*)d_in[5];
    const float* Whh1 = (const float*)d_in[6];
    const float* bih1 = (const float*)d_in[7];
    const float* bhh1 = (const float*)d_in[8];
    const float* Wih2 = (const float*)d_in[9];
    const float* Whh2 = (const float*)d_in[10];
    const float* bih2 = (const float*)d_in[11];
    const float* bhh2 = (const float*)d_in[12];
    const float* W1   = (const float*)d_in[13];
    const float* b1   = (const float*)d_in[14];
    const float* W2   = (const float*)d_in[15];
    const float* b2   = (const float*)d_in[16];

    float *xproj, *h1;
    __nv_bfloat16 *hsHi, *hsLo, *Whi, *Wlo, *Xhi, *Xlo;
    cudaGetSymbolAddress((void**)&xproj, g_xproj);
    cudaGetSymbolAddress((void**)&h1,   g_h1);
    cudaGetSymbolAddress((void**)&hsHi, g_hsHi);
    cudaGetSymbolAddress((void**)&hsLo, g_hsLo);
    cudaGetSymbolAddress((void**)&Whi,  g_Whi);
    cudaGetSymbolAddress((void**)&Wlo,  g_Wlo);
    cudaGetSymbolAddress((void**)&Xhi,  g_Xhi);
    cudaGetSymbolAddress((void**)&Xlo,  g_Xlo);

    cudaFuncSetAttribute(gemm_tc,  cudaFuncAttributeMaxDynamicSharedMemorySize, GEMM_SMEM);
    cudaFuncSetAttribute(lstm_rec, cudaFuncAttributeMaxDynamicSharedMemorySize, REC_SMEM);

    dim3 gg(16, 256);

    // ---- Layer 0 (K = 128; xproj columns n = b*512 + t) ----
    split_bf16<<<(G4 * Fc + 255) / 256, 256>>>(Wih0, Whi, Wlo, G4 * Fc);
    split_bf16<<<(Nf * Fc + 255) / 256, 256>>>(x, Xhi, Xlo, Nf * Fc);
    gemm_tc<<<gg, 256, GEMM_SMEM>>>(Whi, Wlo, Xhi, Xlo, bih0, bhh0, xproj, Fc);
    lstm_rec<<<NCTA, 256, REC_SMEM>>>(xproj, Whh0, hsHi, hsLo, 1);

    // ---- Layer 1 (K = 512; xproj columns n = t*64 + b) ----
    split_bf16<<<(G4 * Hc + 255) / 256, 256>>>(Wih1, Whi, Wlo, G4 * Hc);
    gemm_tc<<<gg, 256, GEMM_SMEM>>>(Whi, Wlo, hsHi, hsLo, bih1, bhh1, xproj, Hc);
    lstm_rec<<<NCTA, 256, REC_SMEM>>>(xproj, Whh1, hsHi, hsLo, 0);

    // ---- Layer 2 ----
    split_bf16<<<(G4 * Hc + 255) / 256, 256>>>(Wih2, Whi, Wlo, G4 * Hc);
    gemm_tc<<<gg, 256, GEMM_SMEM>>>(Whi, Wlo, hsHi, hsLo, bih2, bhh2, xproj, Hc);
    lstm_rec<<<NCTA, 256, REC_SMEM>>>(xproj, Whh2, hsHi, hsLo, 0);

    // ---- FC head ----
    fc1_kernel<<<16, 256>>>(hsHi, hsLo, W1, b1, h1);
    fc2_kernel<<<1, 64>>>(h1, W2, b2, (float*)d_out);
}